// round 4
// baseline (speedup 1.0000x reference)
#include <cuda_runtime.h>
#include <cuda_bf16.h>

#define NN   50000
#define DD   128
#define EE   400000
#define NMOL 256
#define OUTC 32

typedef unsigned long long u64;

// ---------------- device scratch (no allocations allowed) ----------------
__device__ float g_s1[NN * DD];
__device__ float g_s2[NN * DD];
__device__ float g_Abuf[NN * DD];
__device__ float g_mol[NMOL * DD];
__device__ int   g_is64;

// ---------------- f32x2 helpers ----------------
__device__ __forceinline__ void fma2(u64 &d, u64 a, u64 b) {
    asm("fma.rn.f32x2 %0, %1, %2, %0;" : "+l"(d) : "l"(a), "l"(b));
}
__device__ __forceinline__ float sum2(u64 v) {
    float lo, hi;
    asm("mov.b64 {%0,%1}, %2;" : "=f"(lo), "=f"(hi) : "l"(v));
    return lo + hi;
}

// ---------------- index width detection (int32 vs int64) ----------------
__global__ void detect_kernel(const int* p) {
    if (threadIdx.x == 0) {
        int all0 = 1;
        for (int i = 0; i < 64; i++)
            if (p[2 * i + 1] != 0) { all0 = 0; break; }
        g_is64 = all0;  // int64 little-endian: high words all zero (values < N)
    }
}
__device__ __forceinline__ int load_idx(const void* p, int i) {
    if (g_is64) return (int)((const long long*)p)[i];
    return ((const int*)p)[i];
}

// ---------------- zero fill ----------------
__global__ void zero_kernel(float* p, int n) {
    int i = blockIdx.x * blockDim.x + threadIdx.x;
    int stride = gridDim.x * blockDim.x;
    for (; i < n; i += stride) p[i] = 0.f;
}

// ---------------- precompute: A = S @ [Win_top | Win_bot]  ([N,128]x[128,128]) ----------------
#define PC_WSTRIDE 130
#define PC_SSTRIDE 132
#define PC_SMEM_BYTES ((128 * PC_WSTRIDE + 32 * PC_SSTRIDE) * 4)

__global__ __launch_bounds__(256, 2)
void precompute_kernel(const float* __restrict__ s, float* __restrict__ out,
                       const float* __restrict__ Win_t) {
    extern __shared__ float sm[];
    float* wT = sm;                        // [128 j][130]
    float* ss = sm + 128 * PC_WSTRIDE;     // [32 a][132]
    int tid = threadIdx.x;
    int abase = blockIdx.x * 32;

    // stage combined weight transposed: wT[j][k] ; j<64 -> Win[k][j], j>=64 -> Win[128+k][j-64]
    for (int i = tid; i < 128 * 128; i += 256) {
        int k = i >> 7, j = i & 127;
        float v = (j < 64) ? Win_t[k * 64 + j] : Win_t[(128 + k) * 64 + (j - 64)];
        wT[j * PC_WSTRIDE + k] = v;
    }
    for (int i = tid; i < 32 * 128; i += 256) {
        int a = i >> 7, k = i & 127;
        int atom = abase + a;
        ss[a * PC_SSTRIDE + k] = (atom < NN) ? s[(size_t)atom * DD + k] : 0.f;
    }
    __syncthreads();

    int jg = tid & 31;           // j in {jg, jg+32, jg+64, jg+96}
    int a0 = (tid >> 5) * 4;     // 4 atoms
    u64 acc[4][4];
#pragma unroll
    for (int i = 0; i < 4; i++)
#pragma unroll
        for (int c = 0; c < 4; c++) acc[i][c] = 0ull;

#pragma unroll 4
    for (int k = 0; k < 128; k += 2) {
        u64 sp[4], wp[4];
#pragma unroll
        for (int i = 0; i < 4; i++)
            sp[i] = *(const u64*)&ss[(a0 + i) * PC_SSTRIDE + k];
#pragma unroll
        for (int c = 0; c < 4; c++)
            wp[c] = *(const u64*)&wT[(jg + 32 * c) * PC_WSTRIDE + k];
#pragma unroll
        for (int i = 0; i < 4; i++)
#pragma unroll
            for (int c = 0; c < 4; c++)
                fma2(acc[i][c], sp[i], wp[c]);
    }

#pragma unroll
    for (int i = 0; i < 4; i++) {
        int atom = abase + a0 + i;
        if (atom < NN) {
#pragma unroll
            for (int c = 0; c < 4; c++)
                out[(size_t)atom * DD + jg + 32 * c] = sum2(acc[i][c]);
        }
    }
}

// ---------------- edge kernel: 64 edges per block, 256 threads ----------------
#define WSTRIDE 66
#define HSTRIDE 68
#define ES_WHT 0
#define ES_WOT (ES_WHT + 64 * WSTRIDE)
#define ES_H0  (ES_WOT + 128 * WSTRIDE)
#define ES_H1  (ES_H0 + 64 * HSTRIDE)
#define ES_BH  (ES_H1 + 64 * HSTRIDE)
#define ES_BO  (ES_BH + 64)
#define ES_BI  (ES_BO + 128)
#define ES_IDX (ES_BI + 64)
#define ES_TOT (ES_IDX + 128)
#define EDGE_SMEM_BYTES (ES_TOT * 4)

__global__ __launch_bounds__(256, 2)
void edge_kernel(const float* __restrict__ A, float* __restrict__ sn,
                 const void* __restrict__ srcp, const void* __restrict__ dstp,
                 const float* __restrict__ Wh_t, const float* __restrict__ bh_t,
                 const float* __restrict__ Wo_t, const float* __restrict__ bo_t,
                 const float* __restrict__ bi_t) {
    extern __shared__ float sm[];
    float* whT = sm + ES_WHT;   // [64 j][66]
    float* woT = sm + ES_WOT;   // [128 j][66]
    float* h0  = sm + ES_H0;    // [64 e][68]
    float* h1  = sm + ES_H1;    // [64 e][68]
    float* bh  = sm + ES_BH;
    float* bo  = sm + ES_BO;
    float* bi  = sm + ES_BI;
    int*   dsts = (int*)(sm + ES_IDX);
    int*   srcs = dsts + 64;
    int tid = threadIdx.x;
    int eb = blockIdx.x * 64;

    for (int i = tid; i < 64 * 64; i += 256) {
        int k = i >> 6, j = i & 63;
        whT[j * WSTRIDE + k] = Wh_t[i];
    }
    for (int i = tid; i < 64 * 128; i += 256) {
        int k = i >> 7, j = i & 127;
        woT[j * WSTRIDE + k] = Wo_t[i];
    }
    if (tid < 64) {
        bh[tid] = bh_t[tid];
        bi[tid] = bi_t[tid];
        dsts[tid] = load_idx(dstp, eb + tid);
        srcs[tid] = load_idx(srcp, eb + tid);
    }
    if (tid >= 64 && tid < 192) bo[tid - 64] = bo_t[tid - 64];
    __syncthreads();

    // layer 0: h0[e][j] = relu(A[dst][j] + A[src][64+j] + b_in[j]),  j<64
    {
        int e = tid >> 2;
        int j0 = (tid & 3) * 16;
        const float* ad = A + (size_t)dsts[e] * DD;
        const float* as = A + (size_t)srcs[e] * DD + 64;
#pragma unroll
        for (int v = 0; v < 16; v += 4) {
            int j = j0 + v;
            float4 x = *(const float4*)(ad + j);
            float4 y = *(const float4*)(as + j);
            float4 b = *(const float4*)(bi + j);
            float4 r;
            r.x = fmaxf(x.x + y.x + b.x, 0.f);
            r.y = fmaxf(x.y + y.y + b.y, 0.f);
            r.z = fmaxf(x.z + y.z + b.z, 0.f);
            r.w = fmaxf(x.w + y.w + b.w, 0.f);
            *(float4*)&h0[e * HSTRIDE + j] = r;
        }
    }
    __syncthreads();

    // GEMM1: h1 = relu(h0 @ Wh + b_h)   [64e x 64j x 64k]
    {
        int jg = tid & 15;           // j in {jg, jg+16, jg+32, jg+48}
        int e0 = (tid >> 4) * 4;     // 4 edges
        u64 acc[4][4];
#pragma unroll
        for (int i = 0; i < 4; i++)
#pragma unroll
            for (int c = 0; c < 4; c++) acc[i][c] = 0ull;

#pragma unroll 4
        for (int k = 0; k < 64; k += 2) {
            u64 hp[4], wp[4];
#pragma unroll
            for (int i = 0; i < 4; i++)
                hp[i] = *(const u64*)&h0[(e0 + i) * HSTRIDE + k];
#pragma unroll
            for (int c = 0; c < 4; c++)
                wp[c] = *(const u64*)&whT[(jg + 16 * c) * WSTRIDE + k];
#pragma unroll
            for (int i = 0; i < 4; i++)
#pragma unroll
                for (int c = 0; c < 4; c++)
                    fma2(acc[i][c], hp[i], wp[c]);
        }
        __syncthreads();  // h0 reads done before h1 writes alias nothing, but keep order clean
#pragma unroll
        for (int i = 0; i < 4; i++)
#pragma unroll
            for (int c = 0; c < 4; c++) {
                int j = jg + 16 * c;
                h1[(e0 + i) * HSTRIDE + j] = fmaxf(bh[j] + sum2(acc[i][c]), 0.f);
            }
    }
    __syncthreads();

    // GEMM2 + scatter: h2 = relu(h1 @ Wout + b_out); atomic add into sn[dst]
    {
        int jg = tid & 31;           // j in {jg, jg+32, jg+64, jg+96}
        int e0 = (tid >> 5) * 8;     // 8 edges
        u64 acc[8][4];
#pragma unroll
        for (int i = 0; i < 8; i++)
#pragma unroll
            for (int c = 0; c < 4; c++) acc[i][c] = 0ull;

#pragma unroll 2
        for (int k = 0; k < 64; k += 2) {
            u64 hp[8], wp[4];
#pragma unroll
            for (int i = 0; i < 8; i++)
                hp[i] = *(const u64*)&h1[(e0 + i) * HSTRIDE + k];
#pragma unroll
            for (int c = 0; c < 4; c++)
                wp[c] = *(const u64*)&woT[(jg + 32 * c) * WSTRIDE + k];
#pragma unroll
            for (int i = 0; i < 8; i++)
#pragma unroll
                for (int c = 0; c < 4; c++)
                    fma2(acc[i][c], hp[i], wp[c]);
        }

#pragma unroll
        for (int i = 0; i < 8; i++) {
            float* row = sn + (size_t)dsts[e0 + i] * DD;
#pragma unroll
            for (int c = 0; c < 4; c++) {
                int j = jg + 32 * c;
                float v = fmaxf(bo[j] + sum2(acc[i][c]), 0.f);
                atomicAdd(row + j, v);   // REDG (no return)
            }
        }
    }
}

// ---------------- molecule pooling ----------------
__global__ void pool_kernel(const float* __restrict__ s, const void* __restrict__ molp,
                            float* __restrict__ mol) {
    int i = blockIdx.x * blockDim.x + threadIdx.x;
    int stride = gridDim.x * blockDim.x;
    for (; i < NN * DD; i += stride) {
        int atom = i >> 7, j = i & 127;
        int m = load_idx(molp, atom);
        atomicAdd(&mol[m * DD + j], s[i]);
    }
}

// ---------------- final MLP: one block per molecule, 64 threads ----------------
__global__ void mlp_kernel(const float* __restrict__ mol,
                           const float* __restrict__ w1, const float* __restrict__ b1,
                           const float* __restrict__ w2, const float* __restrict__ b2,
                           const float* __restrict__ w3, const float* __restrict__ b3,
                           float* __restrict__ out) {
    __shared__ float mr[128], a1[64], a2[64];
    int m = blockIdx.x, tid = threadIdx.x;
    mr[tid]      = mol[m * DD + tid];
    mr[tid + 64] = mol[m * DD + tid + 64];
    __syncthreads();
    float acc = b1[tid];
    for (int k = 0; k < 128; k++) acc = fmaf(mr[k], w1[k * 64 + tid], acc);
    a1[tid] = fmaxf(acc, 0.f);
    __syncthreads();
    acc = b2[tid];
    for (int k = 0; k < 64; k++) acc = fmaf(a1[k], w2[k * 64 + tid], acc);
    a2[tid] = fmaxf(acc, 0.f);
    __syncthreads();
    if (tid < OUTC) {
        acc = b3[tid];
        for (int k = 0; k < 64; k++) acc = fmaf(a2[k], w3[k * OUTC + tid], acc);
        out[m * OUTC + tid] = acc;
    }
}

// ---------------- host launcher ----------------
extern "C" void kernel_launch(void* const* d_in, const int* in_sizes, int n_in,
                              void* d_out, int out_size) {
    (void)in_sizes; (void)n_in; (void)out_size;
    const float* states = (const float*)d_in[0];
    const float* Win    = (const float*)d_in[1];
    const float* b_in   = (const float*)d_in[2];
    const float* Wh     = (const float*)d_in[3];
    const float* b_h    = (const float*)d_in[4];
    const float* Wout   = (const float*)d_in[5];
    const float* b_out  = (const float*)d_in[6];
    const float* fc1_w  = (const float*)d_in[7];
    const float* fc1_b  = (const float*)d_in[8];
    const float* fc2_w  = (const float*)d_in[9];
    const float* fc2_b  = (const float*)d_in[10];
    const float* out_w  = (const float*)d_in[11];
    const float* out_b  = (const float*)d_in[12];
    const void*  src    = d_in[13];
    const void*  dst    = d_in[14];
    const void*  molid  = d_in[15];
    float* out = (float*)d_out;

    cudaFuncSetAttribute(precompute_kernel,
        cudaFuncAttributeMaxDynamicSharedMemorySize, PC_SMEM_BYTES);
    cudaFuncSetAttribute(edge_kernel,
        cudaFuncAttributeMaxDynamicSharedMemorySize, EDGE_SMEM_BYTES);

    float *s1, *s2, *ab, *mol;
    cudaGetSymbolAddress((void**)&s1, g_s1);
    cudaGetSymbolAddress((void**)&s2, g_s2);
    cudaGetSymbolAddress((void**)&ab, g_Abuf);
    cudaGetSymbolAddress((void**)&mol, g_mol);

    detect_kernel<<<1, 32>>>((const int*)src);

    const int pc_grid = (NN + 31) / 32;        // 1563
    const int e_grid  = EE / 64;               // 6250
    const int z_grid  = 592;                   // grid-stride zero

    const float* sin = states;
    float* bufs[2] = {s1, s2};
    for (int t = 0; t < 3; t++) {
        float* sout = bufs[t & 1];
        precompute_kernel<<<pc_grid, 256, PC_SMEM_BYTES>>>(sin, ab, Win + (size_t)t * 2 * DD * 64);
        zero_kernel<<<z_grid, 256>>>(sout, NN * DD);
        edge_kernel<<<e_grid, 256, EDGE_SMEM_BYTES>>>(
            ab, sout, src, dst,
            Wh + (size_t)t * 64 * 64, b_h + (size_t)t * 64,
            Wout + (size_t)t * 64 * DD, b_out + (size_t)t * DD,
            b_in + (size_t)t * 64);
        sin = sout;
    }

    zero_kernel<<<32, 256>>>(mol, NMOL * DD);
    pool_kernel<<<592, 256>>>(sin, molid, mol);
    mlp_kernel<<<NMOL, 64>>>(mol, fc1_w, fc1_b, fc2_w, fc2_b, out_w, out_b, out);
}

// round 7
// speedup vs baseline: 1.0730x; 1.0730x over previous
#include <cuda_runtime.h>
#include <cuda_bf16.h>

#define NN   50000
#define DD   128
#define EE   400000
#define NMOL 256
#define OUTC 32

typedef unsigned long long u64;

// ---------------- device scratch (no allocations allowed) ----------------
__device__ float g_s1[NN * DD];
__device__ float g_s2[NN * DD];
__device__ float g_Abuf[NN * DD];
__device__ float g_mol[NMOL * DD];
__device__ int   g_is64;

// ---------------- f32x2 helpers ----------------
__device__ __forceinline__ void fma2(u64 &d, u64 a, u64 b) {
    asm("fma.rn.f32x2 %0, %1, %2, %0;" : "+l"(d) : "l"(a), "l"(b));
}
__device__ __forceinline__ float sum2(u64 v) {
    float lo, hi;
    asm("mov.b64 {%0,%1}, %2;" : "=f"(lo), "=f"(hi) : "l"(v));
    return lo + hi;
}

// ---------------- index width detection (int32 vs int64) ----------------
__global__ void detect_kernel(const int* p) {
    if (threadIdx.x == 0) {
        int all0 = 1;
        for (int i = 0; i < 64; i++)
            if (p[2 * i + 1] != 0) { all0 = 0; break; }
        g_is64 = all0;  // int64 little-endian: high words all zero (values < N)
    }
}
__device__ __forceinline__ int load_idx(const void* p, int i) {
    if (g_is64) return (int)((const long long*)p)[i];
    return ((const int*)p)[i];
}

// ---------------- zero fill (vectorized) ----------------
__global__ void zero_kernel(float4* p, int n4) {
    int i = blockIdx.x * blockDim.x + threadIdx.x;
    int stride = gridDim.x * blockDim.x;
    float4 z = make_float4(0.f, 0.f, 0.f, 0.f);
    for (; i < n4; i += stride) p[i] = z;
}

// ================= precompute: A = S @ [Win_top | Win_bot]  ([N,128]x[128,128]) ======
// 64 atoms per block, 256 threads. Register tile: 8 atoms x 4 j per thread.
// k dimension is 128 -> row stride must hold 128 floats (+4 pad, multiple of 4
// so every 16B shared load stays aligned).
#define PC_STRIDE 132
#define PC_SMEM_BYTES ((128 * PC_STRIDE + 64 * PC_STRIDE) * 4)

__global__ __launch_bounds__(256, 2)
void precompute_kernel(const float* __restrict__ s, float* __restrict__ out,
                       const float* __restrict__ Win_t) {
    extern __shared__ float sm[];
    float* wT = sm;                        // [128 j][132]  k in [0,128)
    float* ss = sm + 128 * PC_STRIDE;      // [64 a][132]   k in [0,128)
    int tid = threadIdx.x;
    int abase = blockIdx.x * 64;

    // stage combined weight transposed: wT[j][k]; j<64 -> Win[k][j], j>=64 -> Win[128+k][j-64]
    for (int i = tid; i < 128 * 128; i += 256) {
        int k = i >> 7, j = i & 127;
        float v = (j < 64) ? Win_t[k * 64 + j] : Win_t[(128 + k) * 64 + (j - 64)];
        wT[j * PC_STRIDE + k] = v;
    }
    // stage 64 state rows (float4)
    for (int i = tid; i < 64 * 32; i += 256) {
        int a = i >> 5, kq = (i & 31) * 4;
        int atom = abase + a;
        float4 v = (atom < NN) ? *(const float4*)&s[(size_t)atom * DD + kq]
                               : make_float4(0.f, 0.f, 0.f, 0.f);
        *(float4*)&ss[a * PC_STRIDE + kq] = v;
    }
    __syncthreads();

    int jg = tid & 31;           // j in {jg, jg+32, jg+64, jg+96}
    int a0 = (tid >> 5) * 8;     // 8 atoms
    u64 acc[8][4];
#pragma unroll
    for (int i = 0; i < 8; i++)
#pragma unroll
        for (int c = 0; c < 4; c++) acc[i][c] = 0ull;

#pragma unroll 2
    for (int k = 0; k < 128; k += 4) {
        ulonglong2 wp[4];
#pragma unroll
        for (int c = 0; c < 4; c++)
            wp[c] = *(const ulonglong2*)&wT[(jg + 32 * c) * PC_STRIDE + k];
#pragma unroll
        for (int h = 0; h < 2; h++) {
#pragma unroll
            for (int i = 0; i < 4; i++) {
                int r = h * 4 + i;
                ulonglong2 hv = *(const ulonglong2*)&ss[(a0 + r) * PC_STRIDE + k];
#pragma unroll
                for (int c = 0; c < 4; c++) {
                    fma2(acc[r][c], hv.x, wp[c].x);
                    fma2(acc[r][c], hv.y, wp[c].y);
                }
            }
        }
    }

#pragma unroll
    for (int i = 0; i < 8; i++) {
        int atom = abase + a0 + i;
        if (atom < NN) {
#pragma unroll
            for (int c = 0; c < 4; c++)
                out[(size_t)atom * DD + jg + 32 * c] = sum2(acc[i][c]);
        }
    }
}

// ================= edge kernel: 64 edges per block, 256 threads ======================
// All k extents here are <= 64, so stride 68 (multiple of 4 for 16B alignment) is safe.
#define WSTRIDE 68
#define HSTRIDE 68
#define ES_WHT 0
#define ES_WOT (ES_WHT + 64 * WSTRIDE)
#define ES_H   (ES_WOT + 128 * WSTRIDE)
#define ES_BH  (ES_H + 64 * HSTRIDE)
#define ES_BO  (ES_BH + 64)
#define ES_BI  (ES_BO + 128)
#define ES_IDX (ES_BI + 64)
#define ES_TOT (ES_IDX + 128)
#define EDGE_SMEM_BYTES (ES_TOT * 4)

__global__ __launch_bounds__(256, 2)
void edge_kernel(const float* __restrict__ A, float* __restrict__ sn,
                 const void* __restrict__ srcp, const void* __restrict__ dstp,
                 const float* __restrict__ Wh_t, const float* __restrict__ bh_t,
                 const float* __restrict__ Wo_t, const float* __restrict__ bo_t,
                 const float* __restrict__ bi_t) {
    extern __shared__ float sm[];
    float* whT = sm + ES_WHT;   // [64 j][68]   k<64
    float* woT = sm + ES_WOT;   // [128 j][68]  k<64
    float* hb  = sm + ES_H;     // [64 e][68]   (h0, then overwritten by h1)
    float* bh  = sm + ES_BH;
    float* bo  = sm + ES_BO;
    float* bi  = sm + ES_BI;
    int*   dsts = (int*)(sm + ES_IDX);
    int*   srcs = dsts + 64;
    int tid = threadIdx.x;
    int eb = blockIdx.x * 64;

    for (int i = tid; i < 64 * 64; i += 256) {
        int k = i >> 6, j = i & 63;
        whT[j * WSTRIDE + k] = Wh_t[i];
    }
    for (int i = tid; i < 64 * 128; i += 256) {
        int k = i >> 7, j = i & 127;
        woT[j * WSTRIDE + k] = Wo_t[i];
    }
    if (tid < 64) {
        bh[tid] = bh_t[tid];
        bi[tid] = bi_t[tid];
        dsts[tid] = load_idx(dstp, eb + tid);
        srcs[tid] = load_idx(srcp, eb + tid);
    }
    if (tid >= 64 && tid < 192) bo[tid - 64] = bo_t[tid - 64];
    __syncthreads();

    // layer 0: hb[e][j] = relu(A[dst][j] + A[src][64+j] + b_in[j]),  j<64
    {
        int e = tid >> 2;
        int j0 = (tid & 3) * 16;
        const float* ad = A + (size_t)dsts[e] * DD;
        const float* as = A + (size_t)srcs[e] * DD + 64;
#pragma unroll
        for (int v = 0; v < 16; v += 4) {
            int j = j0 + v;
            float4 x = *(const float4*)(ad + j);
            float4 y = *(const float4*)(as + j);
            float4 b = *(const float4*)(bi + j);
            float4 r;
            r.x = fmaxf(x.x + y.x + b.x, 0.f);
            r.y = fmaxf(x.y + y.y + b.y, 0.f);
            r.z = fmaxf(x.z + y.z + b.z, 0.f);
            r.w = fmaxf(x.w + y.w + b.w, 0.f);
            *(float4*)&hb[e * HSTRIDE + j] = r;
        }
    }
    __syncthreads();

    // GEMM1: h1 = relu(h0 @ Wh + b_h)   [64e x 64j x 64k], h1 overwrites h0 after barrier
    {
        int jg = tid & 15;           // j in {jg, jg+16, jg+32, jg+48}
        int e0 = (tid >> 4) * 4;     // 4 edges
        u64 acc[4][4];
#pragma unroll
        for (int i = 0; i < 4; i++)
#pragma unroll
            for (int c = 0; c < 4; c++) acc[i][c] = 0ull;

#pragma unroll 4
        for (int k = 0; k < 64; k += 4) {
            ulonglong2 wp[4];
#pragma unroll
            for (int c = 0; c < 4; c++)
                wp[c] = *(const ulonglong2*)&whT[(jg + 16 * c) * WSTRIDE + k];
#pragma unroll
            for (int i = 0; i < 4; i++) {
                ulonglong2 hv = *(const ulonglong2*)&hb[(e0 + i) * HSTRIDE + k];
#pragma unroll
                for (int c = 0; c < 4; c++) {
                    fma2(acc[i][c], hv.x, wp[c].x);
                    fma2(acc[i][c], hv.y, wp[c].y);
                }
            }
        }
        __syncthreads();   // all h0 reads complete before h1 overwrites the buffer
#pragma unroll
        for (int i = 0; i < 4; i++)
#pragma unroll
            for (int c = 0; c < 4; c++) {
                int j = jg + 16 * c;
                hb[(e0 + i) * HSTRIDE + j] = fmaxf(bh[j] + sum2(acc[i][c]), 0.f);
            }
    }
    __syncthreads();

    // GEMM2 + scatter: h2 = relu(h1 @ Wout + b_out); atomic add into sn[dst]
    {
        int jg = tid & 31;           // j in {jg, jg+32, jg+64, jg+96}
        int e0 = (tid >> 5) * 8;     // 8 edges (warp-uniform -> hb loads broadcast)
        u64 acc[8][4];
#pragma unroll
        for (int i = 0; i < 8; i++)
#pragma unroll
            for (int c = 0; c < 4; c++) acc[i][c] = 0ull;

#pragma unroll 2
        for (int k = 0; k < 64; k += 4) {
            ulonglong2 wp[4];
#pragma unroll
            for (int c = 0; c < 4; c++)
                wp[c] = *(const ulonglong2*)&woT[(jg + 32 * c) * WSTRIDE + k];
#pragma unroll
            for (int h = 0; h < 2; h++) {
#pragma unroll
                for (int i = 0; i < 4; i++) {
                    int r = h * 4 + i;
                    ulonglong2 hv = *(const ulonglong2*)&hb[(e0 + r) * HSTRIDE + k];
#pragma unroll
                    for (int c = 0; c < 4; c++) {
                        fma2(acc[r][c], hv.x, wp[c].x);
                        fma2(acc[r][c], hv.y, wp[c].y);
                    }
                }
            }
        }

#pragma unroll
        for (int i = 0; i < 8; i++) {
            float* row = sn + (size_t)dsts[e0 + i] * DD;
#pragma unroll
            for (int c = 0; c < 4; c++) {
                int j = jg + 32 * c;
                float v = fmaxf(bo[j] + sum2(acc[i][c]), 0.f);
                atomicAdd(row + j, v);   // REDG, warp-coalesced over j
            }
        }
    }
}

// ---------------- molecule pooling ----------------
__global__ void pool_kernel(const float* __restrict__ s, const void* __restrict__ molp,
                            float* __restrict__ mol) {
    int i = blockIdx.x * blockDim.x + threadIdx.x;
    int stride = gridDim.x * blockDim.x;
    for (; i < NN * 32; i += stride) {
        int atom = i >> 5, q = (i & 31) * 4;
        int m = load_idx(molp, atom);
        float4 v = *(const float4*)&s[(size_t)atom * DD + q];
        float* row = &mol[m * DD + q];
        atomicAdd(row + 0, v.x);
        atomicAdd(row + 1, v.y);
        atomicAdd(row + 2, v.z);
        atomicAdd(row + 3, v.w);
    }
}

// ---------------- final MLP: one block per molecule, 64 threads ----------------
__global__ void mlp_kernel(const float* __restrict__ mol,
                           const float* __restrict__ w1, const float* __restrict__ b1,
                           const float* __restrict__ w2, const float* __restrict__ b2,
                           const float* __restrict__ w3, const float* __restrict__ b3,
                           float* __restrict__ out) {
    __shared__ float mr[128], a1[64], a2[64];
    int m = blockIdx.x, tid = threadIdx.x;
    mr[tid]      = mol[m * DD + tid];
    mr[tid + 64] = mol[m * DD + tid + 64];
    __syncthreads();
    float acc = b1[tid];
    for (int k = 0; k < 128; k++) acc = fmaf(mr[k], w1[k * 64 + tid], acc);
    a1[tid] = fmaxf(acc, 0.f);
    __syncthreads();
    acc = b2[tid];
    for (int k = 0; k < 64; k++) acc = fmaf(a1[k], w2[k * 64 + tid], acc);
    a2[tid] = fmaxf(acc, 0.f);
    __syncthreads();
    if (tid < OUTC) {
        acc = b3[tid];
        for (int k = 0; k < 64; k++) acc = fmaf(a2[k], w3[k * OUTC + tid], acc);
        out[m * OUTC + tid] = acc;
    }
}

// ---------------- host launcher ----------------
extern "C" void kernel_launch(void* const* d_in, const int* in_sizes, int n_in,
                              void* d_out, int out_size) {
    (void)in_sizes; (void)n_in; (void)out_size;
    const float* states = (const float*)d_in[0];
    const float* Win    = (const float*)d_in[1];
    const float* b_in   = (const float*)d_in[2];
    const float* Wh     = (const float*)d_in[3];
    const float* b_h    = (const float*)d_in[4];
    const float* Wout   = (const float*)d_in[5];
    const float* b_out  = (const float*)d_in[6];
    const float* fc1_w  = (const float*)d_in[7];
    const float* fc1_b  = (const float*)d_in[8];
    const float* fc2_w  = (const float*)d_in[9];
    const float* fc2_b  = (const float*)d_in[10];
    const float* out_w  = (const float*)d_in[11];
    const float* out_b  = (const float*)d_in[12];
    const void*  src    = d_in[13];
    const void*  dst    = d_in[14];
    const void*  molid  = d_in[15];
    float* out = (float*)d_out;

    cudaFuncSetAttribute(precompute_kernel,
        cudaFuncAttributeMaxDynamicSharedMemorySize, PC_SMEM_BYTES);
    cudaFuncSetAttribute(edge_kernel,
        cudaFuncAttributeMaxDynamicSharedMemorySize, EDGE_SMEM_BYTES);

    float *s1, *s2, *ab, *mol;
    cudaGetSymbolAddress((void**)&s1, g_s1);
    cudaGetSymbolAddress((void**)&s2, g_s2);
    cudaGetSymbolAddress((void**)&ab, g_Abuf);
    cudaGetSymbolAddress((void**)&mol, g_mol);

    detect_kernel<<<1, 32>>>((const int*)src);

    const int pc_grid = (NN + 63) / 64;        // 782
    const int e_grid  = EE / 64;               // 6250
    const int z_grid  = 296;

    const float* sin = states;
    float* bufs[2] = {s1, s2};
    for (int t = 0; t < 3; t++) {
        float* sout = bufs[t & 1];
        precompute_kernel<<<pc_grid, 256, PC_SMEM_BYTES>>>(sin, ab, Win + (size_t)t * 2 * DD * 64);
        zero_kernel<<<z_grid, 256>>>((float4*)sout, NN * DD / 4);
        edge_kernel<<<e_grid, 256, EDGE_SMEM_BYTES>>>(
            ab, sout, src, dst,
            Wh + (size_t)t * 64 * 64, b_h + (size_t)t * 64,
            Wout + (size_t)t * 64 * DD, b_out + (size_t)t * DD,
            b_in + (size_t)t * 64);
        sin = sout;
    }

    zero_kernel<<<8, 256>>>((float4*)mol, NMOL * DD / 4);
    pool_kernel<<<592, 256>>>(sin, molid, mol);
    mlp_kernel<<<NMOL, 64>>>(mol, fc1_w, fc1_b, fc2_w, fc2_b, out_w, out_b, out);
}